// round 5
// baseline (speedup 1.0000x reference)
#include <cuda_runtime.h>
#include <stdint.h>
#include <math.h>

#define Bv 16
#define Hv 512
#define Wv 512
#define Cv 3
#define TOT (Bv*Hv*Wv*Cv)   // 12,582,912
#define NPLANES (Bv*Cv)     // 48

// Scratch (device globals -- no runtime allocation allowed)
__device__ uint32_t g_weakbits[NPLANES * Hv * 16];    // 16 u32 words per row
__device__ uint32_t g_strongbits[NPLANES * Hv * 16];

// ---------------- error-free compensated summation (pure f32, exact products)
__device__ __forceinline__ void two_sum(float a, float b, float& s, float& e) {
    s = __fadd_rn(a, b);
    float bb = __fsub_rn(s, a);
    e = __fadd_rn(__fsub_rn(a, __fsub_rn(s, bb)), __fsub_rn(b, bb));
}

template <int N>
__device__ __forceinline__ float sum_exact(const float* t) {
    float s = t[0], e = 0.f;
#pragma unroll
    for (int i = 1; i < N; ++i) {
        float ei;
        two_sum(s, t[i], s, ei);
        e = __fadd_rn(e, ei);
    }
    return __fadd_rn(s, e);   // correctly-rounded sum (ORO Sum2)
}

// ========== K1: blur + sobel + mag + sector + NMS + threshold (fully fused) ==
// Inner tile 32x32 pixels x 3ch. Halo cells are addressed TOROIDALLY (matches
// jnp.roll); zero-pad masks are evaluated at the wrapped real coordinate, so
// halo values are bitwise identical to computing them in their home tile.
#define TY 32
#define TX 32
#define SIW 114   // 38*3  input smem row width (interleaved c)
#define SLW 108   // 36*3  blurred
#define SMW 102   // 34*3  magnitude

__device__ __forceinline__ void sobel_at(const float* sb, int bi,
                                         bool ym, bool yp, bool xm, bool xp,
                                         float& gx, float& gy) {
    float v00 = (ym && xm) ? sb[bi - SLW - 3] : 0.f;
    float v01 =  ym        ? sb[bi - SLW]     : 0.f;
    float v02 = (ym && xp) ? sb[bi - SLW + 3] : 0.f;
    float v10 =  xm        ? sb[bi - 3]       : 0.f;
    float v12 =  xp        ? sb[bi + 3]       : 0.f;
    float v20 = (yp && xm) ? sb[bi + SLW - 3] : 0.f;
    float v21 =  yp        ? sb[bi + SLW]     : 0.f;
    float v22 = (yp && xp) ? sb[bi + SLW + 3] : 0.f;
    {
        float tx[6] = { -v00, v02, __fmul_rn(-2.f, v10), __fmul_rn(2.f, v12), -v20, v22 };
        gx = sum_exact<6>(tx);
    }
    {
        float ty[6] = { -v00, __fmul_rn(-2.f, v01), -v02, v20, __fmul_rn(2.f, v21), v22 };
        gy = sum_exact<6>(ty);
    }
}

__device__ __forceinline__ float mag_of(float gx, float gy) {
    float s = __fadd_rn(__fmul_rn(gx, gx), __fmul_rn(gy, gy));
    return __fsqrt_rn(s);
}

__global__ void __launch_bounds__(256) canny_k(const float* __restrict__ x) {
    __shared__ float si[38 * SIW];    // rows wrap(y0-3 .. y0+34), cols wrap(x0-3 .. x0+34)
    __shared__ float sl[36 * SLW];    // blur, wrap(y0-2 .. y0+33)
    __shared__ float sm[34 * SMW];    // mag,  wrap(y0-1 .. y0+32)
    int tid = threadIdx.x;
    int x0 = blockIdx.x * TX;
    int y0 = blockIdx.y * TY;
    int b  = blockIdx.z;
    const float* base = x + (size_t)b * Hv * Wv * 3;

    // load input toroidally (values at wrapped coords; masking happens later)
    for (int i = tid; i < 38 * SIW; i += 256) {
        int r = i / SIW, col = i - r * SIW;
        int lx = col / 3, c = col - lx * 3;
        int gy = (y0 + r - 3) & 511;
        int gx = (x0 + lx - 3) & 511;
        si[i] = __ldg(base + (gy * Wv + gx) * 3 + c);
    }
    __syncthreads();

    // blur (correctly rounded); zero-pad masks at the wrapped real coordinate
    for (int i = tid; i < 36 * SLW; i += 256) {
        int r = i / SLW, col = i - r * SLW;
        int lx = col / 3, c = col - lx * 3;
        int py = (y0 + r - 2) & 511;
        int px = (x0 + lx - 2) & 511;
        int ii = (r + 1) * SIW + (lx + 1) * 3 + c;
        float t[9];
        int k = 0;
#pragma unroll
        for (int dy = -1; dy <= 1; ++dy) {
            bool yok = (unsigned)(py + dy) < (unsigned)Hv;
#pragma unroll
            for (int dx = -1; dx <= 1; ++dx) {
                bool ok = yok && ((unsigned)(px + dx) < (unsigned)Wv);
                float v = ok ? si[ii + dy * SIW + dx * 3] : 0.f;
                float w = (dy == 0) ? ((dx == 0) ? 0.25f : 0.125f)
                                    : ((dx == 0) ? 0.125f : 0.0625f);
                t[k++] = __fmul_rn(v, w);
            }
        }
        sl[i] = sum_exact<9>(t);
    }
    __syncthreads();

    // sobel + magnitude on the 34x34 halo region (masks at wrapped real coord)
    for (int i = tid; i < 34 * SMW; i += 256) {
        int r = i / SMW, col = i - r * SMW;
        int lx = col / 3, c = col - lx * 3;
        int my = (y0 + r - 1) & 511;
        int mx = (x0 + lx - 1) & 511;
        int bi = (r + 1) * SLW + (lx + 1) * 3 + c;
        float gxv, gyv;
        sobel_at(sl, bi, my > 0, my < 511, mx > 0, mx < 511, gxv, gyv);
        sm[i] = mag_of(gxv, gyv);
    }
    __syncthreads();

    // NMS + double threshold on inner 32x32x3; ballot into bit planes
    const float SCALE = (float)(180.0 / 3.14159);
    uint32_t lane = tid & 31;
#pragma unroll
    for (int k = 0; k < 12; ++k) {
        int p = k * 256 + tid;           // 0..3071
        int x5 = p & 31;                 // lane == x5
        int t2 = p >> 5;                 // 0..95
        int row = t2 & 31;
        int c = t2 >> 5;                 // 0..2
        int iy = y0 + row, ix = x0 + x5;
        int bi = (row + 2) * SLW + (x5 + 2) * 3 + c;   // blur center at inner pixel
        float gxv, gyv;
        sobel_at(sl, bi, iy > 0, iy < 511, ix > 0, ix < 511, gxv, gyv);

        float ang = __fmul_rn(atan2f(gyv, gxv), SCALE);
        if (ang < 0.f) ang = __fadd_rn(ang, 180.f);

        int mi = (row + 1) * SMW + (x5 + 1) * 3 + c;
        float m = sm[mi];
        float na, nb;
        if (ang <= 22.5f || ang > 157.5f) { na = sm[mi + 3];       nb = sm[mi - 3]; }
        else if (ang <= 67.5f)            { na = sm[mi + SMW - 3]; nb = sm[mi - SMW + 3]; }
        else if (ang <= 112.5f)           { na = sm[mi + SMW];     nb = sm[mi - SMW]; }
        else                              { na = sm[mi + SMW + 3]; nb = sm[mi - SMW - 3]; }
        float sup = (m >= na && m >= nb) ? m : 0.f;
        bool strong = sup >= 0.3f;
        bool weak   = (sup >= 0.1f) && !strong;
        uint32_t wbal = __ballot_sync(0xFFFFFFFFu, weak);
        uint32_t sbal = __ballot_sync(0xFFFFFFFFu, strong);
        if (lane == 0) {
            int idx = (((b * 3 + c) << 9) + iy) * 16 + (x0 >> 5);
            g_weakbits[idx] = wbal;
            g_strongbits[idx] = sbal;
        }
    }
}

// ============================ K3: hysteresis on bitboards ====================
__device__ __forceinline__ void hexpand8(const uint64_t* S, uint64_t* E) {
#pragma unroll
    for (int j = 0; j < 8; ++j) {
        uint64_t s = S[j];
        uint64_t l = (s << 1) | (S[(j + 7) & 7] >> 63);   // neighbor x-1
        uint64_t r = (s >> 1) | (S[(j + 1) & 7] << 63);   // neighbor x+1
        E[j] = s | l | r;
    }
}

// row-local closure: promote weak bits connected horizontally to strong
__device__ __forceinline__ void row_closure(uint64_t* S, const uint64_t* W) {
    for (;;) {
        uint64_t E[8];
        hexpand8(S, E);
        uint64_t any = 0;
#pragma unroll
        for (int j = 0; j < 8; ++j) {
            uint64_t n = W[j] & E[j] & ~S[j];
            any |= n;
            S[j] |= n;
        }
        if (!any) break;
    }
}

__global__ void __launch_bounds__(512) hyst_k() {
    __shared__ uint64_t H[512][8];
    int row = threadIdx.x;          // one row per thread
    int plane = blockIdx.x;
    int base = ((plane << 9) + row) * 16;

    uint64_t S[8], W[8];
#pragma unroll
    for (int j = 0; j < 8; ++j) {
        S[j] = (uint64_t)g_strongbits[base + 2 * j] |
               ((uint64_t)g_strongbits[base + 2 * j + 1] << 32);
        W[j] = (uint64_t)g_weakbits[base + 2 * j] |
               ((uint64_t)g_weakbits[base + 2 * j + 1] << 32);
    }
    row_closure(S, W);

    int up = (row + 511) & 511;
    int dn = (row + 1) & 511;

    for (;;) {
        uint64_t E[8];
        hexpand8(S, E);
#pragma unroll
        for (int j = 0; j < 8; ++j) H[row][j] = E[j];
        __syncthreads();
        uint64_t any = 0;
#pragma unroll
        for (int j = 0; j < 8; ++j) {
            uint64_t n = W[j] & (H[up][j] | H[dn][j]) & ~S[j];
            any |= n;
            S[j] |= n;
        }
        if (any) row_closure(S, W);
        if (!__syncthreads_or(any != 0)) break;
    }

#pragma unroll
    for (int j = 0; j < 8; ++j) {
        g_strongbits[base + 2 * j]     = (uint32_t)S[j];
        g_strongbits[base + 2 * j + 1] = (uint32_t)(S[j] >> 32);
    }
}

// ============================ K4: expand strong bits -> f32 NHWC (vec4) ======
__global__ void __launch_bounds__(384) out_k(float4* __restrict__ out) {
    __shared__ uint32_t srow[48];     // 3 channels x 16 words for this (b,y) row
    int rowid = blockIdx.x;           // 0..8191 = b*512 + y
    int b = rowid >> 9, y = rowid & 511;
    int tid = threadIdx.x;
    if (tid < 48) {
        int c = tid >> 4, w = tid & 15;
        srow[tid] = g_strongbits[(((b * 3 + c) << 9) + y) * 16 + w];
    }
    __syncthreads();
    int e = tid * 4;                  // element within the 1536-float row
    float4 v;
    float* vp = (float*)&v;
#pragma unroll
    for (int k = 0; k < 4; ++k) {
        int ee = e + k;
        int xx = (ee * 21846) >> 16;  // ee/3 for ee < 32768
        int c  = ee - 3 * xx;
        vp[k] = ((srow[(c << 4) + (xx >> 5)] >> (xx & 31)) & 1u) ? 1.f : 0.f;
    }
    out[(size_t)rowid * 384 + tid] = v;
}

// --------------------------------------------------------------- launch
extern "C" void kernel_launch(void* const* d_in, const int* in_sizes, int n_in,
                              void* d_out, int out_size) {
    const float* x = (const float*)d_in[0];

    dim3 g1(Wv / TX, Hv / TY, Bv);
    canny_k<<<g1, 256>>>(x);

    hyst_k<<<NPLANES, 512>>>();

    out_k<<<Bv * Hv, 384>>>((float4*)d_out);
}